// round 14
// baseline (speedup 1.0000x reference)
#include <cuda_runtime.h>
#include <cuda_bf16.h>
#include <cstdint>

#define NN   100000      // nodes
#define NE   3200000     // edges (without self loops)
#define NPAD 100096      // nodes padded for GEMM tiles
#define NG   128         // graphs
#define FIN  768
#define F1   128
#define SCAN_CHUNK 1024
#define NB   ((NN + SCAN_CHUNK - 1) / SCAN_CHUNK)   // 98 scan blocks
#define GEMM_BLOCKS (NPAD / 64)                     // 1564 (M64 tiles)

// ---------------- scratch (device globals; no allocations allowed) ----------------
__device__ alignas(16) int   g_csr[NE];
__device__ alignas(16) int   g_degi[NN];
__device__ alignas(16) int   g_cur[NN];
__device__ alignas(16) int   g_off[NN + 1];
__device__ alignas(16) int   g_bsum[NB];
__device__ alignas(16) float g_dinv[NN];
__device__ alignas(16) __nv_bfloat16 g_h1b[(size_t)NN * F1];   // bf16 h1 (25.6MB, L2-resident)
__device__ alignas(16) float g_h2[(size_t)NN * 2];
__device__ alignas(16) __nv_bfloat16 g_W1bT[(size_t)F1 * FIN]; // W1 transposed [128][768]
__device__ alignas(16) float g_pool[NG * 2];
__device__ alignas(16) float g_cnt[NG];

// ---------------- K0: zero scratch + W1 [768,128] fp32 -> W1T [128,768] bf16 -------
__global__ void zero_w1t_kernel(const float* __restrict__ W1) {
    int i = blockIdx.x * blockDim.x + threadIdx.x;
    if (i < NN) g_degi[i] = 0;
    if (i < NG * 2) g_pool[i] = 0.0f;
    if (i < NG) g_cnt[i] = 0.0f;
    if (i < FIN * F1) {
        int n = i / FIN;
        int k = i - n * FIN;
        g_W1bT[i] = __float2bfloat16(W1[(size_t)k * F1 + n]);
    }
}

// ---------------- K1: degree histogram over destination column (int32 edges) ------
__global__ void hist_kernel(const int* __restrict__ ei) {
    int e = blockIdx.x * blockDim.x + threadIdx.x;
    if (e < NE) {
        int c = ei[NE + e];
        c = min(max(c, 0), NN - 1);     // defensive: never scatter OOB
        atomicAdd(&g_degi[c], 1);
    }
}

// ---------------- K2a: per-block local exclusive scan (1024 elems/block) + dinv ----
__global__ __launch_bounds__(256) void scanA_kernel() {
    __shared__ int wsum[8];
    int tid = threadIdx.x, lane = tid & 31, wid = tid >> 5;
    int i0 = blockIdx.x * SCAN_CHUNK + tid * 4;
    int v0 = (i0 + 0 < NN) ? g_degi[i0 + 0] : 0;
    int v1 = (i0 + 1 < NN) ? g_degi[i0 + 1] : 0;
    int v2 = (i0 + 2 < NN) ? g_degi[i0 + 2] : 0;
    int v3 = (i0 + 3 < NN) ? g_degi[i0 + 3] : 0;
    int t = v0 + v1 + v2 + v3;
    int s = t;
#pragma unroll
    for (int o = 1; o < 32; o <<= 1) {
        int u = __shfl_up_sync(0xffffffffu, s, o);
        if (lane >= o) s += u;
    }
    if (lane == 31) wsum[wid] = s;
    __syncthreads();
    if (wid == 0 && lane < 8) {
        int ws = wsum[lane];
#pragma unroll
        for (int o = 1; o < 8; o <<= 1) {
            int u = __shfl_up_sync(0xffu, ws, o);
            if (lane >= o) ws += u;
        }
        wsum[lane] = ws;
    }
    __syncthreads();
    int warpbase = wid ? wsum[wid - 1] : 0;
    int excl = warpbase + (s - t);                 // local exclusive prefix
    int e0 = excl, e1 = e0 + v0, e2 = e1 + v1, e3 = e2 + v2;
    if (i0 + 0 < NN) { g_off[i0 + 0] = e0; g_dinv[i0 + 0] = rsqrtf((float)(v0 + 1)); }
    if (i0 + 1 < NN) { g_off[i0 + 1] = e1; g_dinv[i0 + 1] = rsqrtf((float)(v1 + 1)); }
    if (i0 + 2 < NN) { g_off[i0 + 2] = e2; g_dinv[i0 + 2] = rsqrtf((float)(v2 + 1)); }
    if (i0 + 3 < NN) { g_off[i0 + 3] = e3; g_dinv[i0 + 3] = rsqrtf((float)(v3 + 1)); }
    if (tid == 255) g_bsum[blockIdx.x] = wsum[7];  // block total
}

// ---------------- K2b: add block bases (each block warp-reduces its prefix) --------
__global__ __launch_bounds__(256) void scanC_kernel() {
    int blk = blockIdx.x;
    int chunk = blk >> 2;                 // 256-thread block sits inside one 1024-chunk
    int lane = threadIdx.x & 31;
    int acc = 0;
    for (int b = lane; b < chunk; b += 32) acc += g_bsum[b];
#pragma unroll
    for (int o = 16; o > 0; o >>= 1) acc += __shfl_xor_sync(0xffffffffu, acc, o);
    int i = blk * 256 + threadIdx.x;
    if (i < NN) {
        int o = g_off[i] + acc;
        g_off[i] = o;
        g_cur[i] = o;
    }
    if (i == 0) g_off[NN] = NE;
}

// ---------------- K3: fill CSR (bucketize source rows by destination col) ----------
__global__ void fill_csr_kernel(const int* __restrict__ ei) {
    int e = blockIdx.x * blockDim.x + threadIdx.x;
    if (e < NE) {
        int r = ei[e];
        int c = ei[NE + e];
        r = min(max(r, 0), NN - 1);
        c = min(max(c, 0), NN - 1);
        int pos = atomicAdd(&g_cur[c], 1);
        g_csr[pos] = r;
    }
}

// ---------------- K4: GEMM h1 = bf16(x) @ bf16(W1) -> bf16, mma.sync ---------------
// M64xN128 tile per CTA (acc 32 regs/thread, ~90 total) so that 2 gemm CTAs/SM
// leave register headroom for branch-B (hist/fill) CTAs to co-reside.
__device__ __forceinline__ void mma16816(float* d, const uint32_t* a, const uint32_t* b) {
    asm volatile(
        "mma.sync.aligned.m16n8k16.row.col.f32.bf16.bf16.f32 "
        "{%0,%1,%2,%3}, {%4,%5,%6,%7}, {%8,%9}, {%0,%1,%2,%3};\n"
        : "+f"(d[0]), "+f"(d[1]), "+f"(d[2]), "+f"(d[3])
        : "r"(a[0]), "r"(a[1]), "r"(a[2]), "r"(a[3]), "r"(b[0]), "r"(b[1]));
}

__global__ __launch_bounds__(256, 2) void gemm_kernel(const float* __restrict__ x) {
    __shared__ alignas(16) __nv_bfloat16 As[64][40];    // 64 rows x 32 k (stride 40)
    __shared__ alignas(16) __nv_bfloat16 Bt[128][40];   // 128 n   x 32 k

    int tid = threadIdx.x;
    int warp = tid >> 5, lane = tid & 31;
    int wm = warp & 3;            // 4 warps over M (16 rows each)
    int wn = warp >> 2;           // 2 warps over N (64 cols each)
    int blockM = blockIdx.x * 64;
    int gid = lane >> 2;          // group id 0..7
    int qid = lane & 3;           // thread-in-group 0..3

    float acc[8][4];
#pragma unroll
    for (int nt = 0; nt < 8; nt++)
#pragma unroll
        for (int i = 0; i < 4; i++) acc[nt][i] = 0.0f;

    // staging maps: A — warp covers 4 consecutive rows (8 lanes x float4 = 128B/row)
    int srow = tid >> 3;          // 0..31 (pass p adds p*32)
    int sl8  = tid & 7;           // 0..7
    // B — 4 lanes x uint4 per n-row, 8 rows per warp
    int bn   = tid >> 2;          // 0..63 (pass s adds s*64)
    int bq   = tid & 3;           // 0..3

    const float* xbase = x + (size_t)blockM * FIN;

    float4 av[2];
    uint4  bv[2];

    // prefetch tile k0 = 0
#pragma unroll
    for (int p = 0; p < 2; p++) {
        int row = p * 32 + srow;
        bool ok = (blockM + row) < NN;
        av[p] = ok ? *(const float4*)(xbase + (size_t)row * FIN + sl8 * 4)
                   : make_float4(0.f, 0.f, 0.f, 0.f);
    }
#pragma unroll
    for (int s = 0; s < 2; s++) {
        int n = s * 64 + bn;
        bv[s] = *(const uint4*)(g_W1bT + (size_t)n * FIN + bq * 8);
    }

    for (int k0 = 0; k0 < FIN; k0 += 32) {
        // commit prefetched tile to smem
#pragma unroll
        for (int p = 0; p < 2; p++) {
            int row = p * 32 + srow;
            *(__nv_bfloat162*)&As[row][sl8 * 4 + 0] = __floats2bfloat162_rn(av[p].x, av[p].y);
            *(__nv_bfloat162*)&As[row][sl8 * 4 + 2] = __floats2bfloat162_rn(av[p].z, av[p].w);
        }
#pragma unroll
        for (int s = 0; s < 2; s++) {
            int n = s * 64 + bn;
            *(uint4*)&Bt[n][bq * 8] = bv[s];
        }
        __syncthreads();

        // issue next tile's global loads (latency hides behind the MMAs below)
        int kn = k0 + 32;
        if (kn < FIN) {
#pragma unroll
            for (int p = 0; p < 2; p++) {
                int row = p * 32 + srow;
                bool ok = (blockM + row) < NN;
                av[p] = ok ? *(const float4*)(xbase + (size_t)row * FIN + kn + sl8 * 4)
                           : make_float4(0.f, 0.f, 0.f, 0.f);
            }
#pragma unroll
            for (int s = 0; s < 2; s++) {
                int n = s * 64 + bn;
                bv[s] = *(const uint4*)(g_W1bT + (size_t)n * FIN + kn + bq * 8);
            }
        }

#pragma unroll
        for (int kk = 0; kk < 32; kk += 16) {
            uint32_t a[4], b[8][2];
            int row = wm * 16 + gid;
            a[0] = *(const uint32_t*)&As[row    ][kk + 2 * qid    ];
            a[1] = *(const uint32_t*)&As[row + 8][kk + 2 * qid    ];
            a[2] = *(const uint32_t*)&As[row    ][kk + 2 * qid + 8];
            a[3] = *(const uint32_t*)&As[row + 8][kk + 2 * qid + 8];
#pragma unroll
            for (int nt = 0; nt < 8; nt++) {
                int n = wn * 64 + nt * 8 + gid;
                b[nt][0] = *(const uint32_t*)&Bt[n][kk + 2 * qid    ];
                b[nt][1] = *(const uint32_t*)&Bt[n][kk + 2 * qid + 8];
            }
#pragma unroll
            for (int nt = 0; nt < 8; nt++)
                mma16816(acc[nt], a, b[nt]);
        }
        __syncthreads();
    }
    // store directly as bf16 h1
    {
        int row = blockM + wm * 16 + gid;
#pragma unroll
        for (int nt = 0; nt < 8; nt++) {
            int col = wn * 64 + nt * 8 + 2 * qid;
            if (row < NN)
                *(__nv_bfloat162*)(g_h1b + (size_t)row * F1 + col) =
                    __floats2bfloat162_rn(acc[nt][0], acc[nt][1]);
            if (row + 8 < NN)
                *(__nv_bfloat162*)(g_h1b + (size_t)(row + 8) * F1 + col) =
                    __floats2bfloat162_rn(acc[nt][2], acc[nt][3]);
        }
    }
}

// ---------------- K5: fused agg1 + b1 + relu + (@W2) -> h2[N,2] ----------------
// one warp per destination node; two edges in flight (one per half-warp);
// each lane owns 8 features (uint4 = 16B), accumulates in packed f32x2.
__device__ __forceinline__ void ffma2(unsigned long long& d, unsigned long long a,
                                      unsigned long long b) {
    asm("fma.rn.f32x2 %0, %1, %2, %0;" : "+l"(d) : "l"(a), "l"(b));
}
__device__ __forceinline__ unsigned long long bf2_to_f32x2(unsigned int v) {
    unsigned int lo = v << 16;
    unsigned int hi = v & 0xffff0000u;
    unsigned long long f2;
    asm("mov.b64 %0, {%1, %2};" : "=l"(f2) : "r"(lo), "r"(hi));
    return f2;
}

__global__ __launch_bounds__(256) void fused1_kernel(const float* __restrict__ b1,
                                                     const float* __restrict__ W2) {
    int warp = (blockIdx.x * blockDim.x + threadIdx.x) >> 5;
    int lane = threadIdx.x & 31;
    if (warp >= NN) return;
    int c = warp;
    float dc = g_dinv[c];
    int start = g_off[c], end = g_off[c + 1];
    int half = lane >> 4;                  // which edge of the pair
    int fl   = lane & 15;                  // feature lane: features fl*8 .. fl*8+7

    unsigned long long acc0 = 0, acc1 = 0, acc2 = 0, acc3 = 0;   // packed f32x2 (zeros)

    int idx = start + lane;
    int rl = (idx < end) ? g_csr[idx] : 0;
    float wl = (idx < end) ? g_dinv[rl] : 0.f;
    for (int base = start; base < end; base += 32) {
        // prefetch next chunk of edge indices/weights
        int nrl = 0; float nwl = 0.f;
        int nidx = base + 32 + lane;
        if (nidx < end) { nrl = g_csr[nidx]; nwl = g_dinv[nrl]; }
#pragma unroll
        for (int jj = 0; jj < 16; jj++) {
            int j = 2 * jj + half;
            int rr = __shfl_sync(0xffffffffu, rl, j);
            float ww = __shfl_sync(0xffffffffu, wl, j);
            unsigned long long wx;
            asm("mov.b64 %0, {%1, %1};" : "=l"(wx) : "f"(ww));
            uint4 p = *(const uint4*)(g_h1b + (size_t)rr * F1 + fl * 8);
            ffma2(acc0, bf2_to_f32x2(p.x), wx);
            ffma2(acc1, bf2_to_f32x2(p.y), wx);
            ffma2(acc2, bf2_to_f32x2(p.z), wx);
            ffma2(acc3, bf2_to_f32x2(p.w), wx);
        }
        rl = nrl; wl = nwl;
    }

    // unpack packed accumulators
    float s[8];
    asm("mov.b64 {%0, %1}, %2;" : "=f"(s[0]), "=f"(s[1]) : "l"(acc0));
    asm("mov.b64 {%0, %1}, %2;" : "=f"(s[2]), "=f"(s[3]) : "l"(acc1));
    asm("mov.b64 {%0, %1}, %2;" : "=f"(s[4]), "=f"(s[5]) : "l"(acc2));
    asm("mov.b64 {%0, %1}, %2;" : "=f"(s[6]), "=f"(s[7]) : "l"(acc3));
    // combine the two half-warp edge partitions (lanes l and l^16 hold same features)
#pragma unroll
    for (int i = 0; i < 8; i++) s[i] += __shfl_xor_sync(0xffffffffu, s[i], 16);

    // self loop: + dinv[c]^2 * h1[c]
    uint4 ps = *(const uint4*)(g_h1b + (size_t)c * F1 + fl * 8);
    float dc2 = dc * dc;
    s[0] += dc2 * __uint_as_float(ps.x << 16);
    s[1] += dc2 * __uint_as_float(ps.x & 0xffff0000u);
    s[2] += dc2 * __uint_as_float(ps.y << 16);
    s[3] += dc2 * __uint_as_float(ps.y & 0xffff0000u);
    s[4] += dc2 * __uint_as_float(ps.z << 16);
    s[5] += dc2 * __uint_as_float(ps.z & 0xffff0000u);
    s[6] += dc2 * __uint_as_float(ps.w << 16);
    s[7] += dc2 * __uint_as_float(ps.w & 0xffff0000u);

    // bias + relu
    int f0 = fl * 8;
    float4 ba = *(const float4*)(b1 + f0);
    float4 bb = *(const float4*)(b1 + f0 + 4);
    float t[8];
    t[0] = fmaxf(dc * s[0] + ba.x, 0.f);
    t[1] = fmaxf(dc * s[1] + ba.y, 0.f);
    t[2] = fmaxf(dc * s[2] + ba.z, 0.f);
    t[3] = fmaxf(dc * s[3] + ba.w, 0.f);
    t[4] = fmaxf(dc * s[4] + bb.x, 0.f);
    t[5] = fmaxf(dc * s[5] + bb.y, 0.f);
    t[6] = fmaxf(dc * s[6] + bb.z, 0.f);
    t[7] = fmaxf(dc * s[7] + bb.w, 0.f);

    // h2 = relu_vec @ W2  (W2 is [128,2] row-major; float4 covers 2 feature rows)
    float o0 = 0.f, o1 = 0.f;
#pragma unroll
    for (int q = 0; q < 4; q++) {
        float4 w = *(const float4*)(W2 + (size_t)(f0 + 2 * q) * 2);
        o0 += t[2 * q] * w.x + t[2 * q + 1] * w.z;
        o1 += t[2 * q] * w.y + t[2 * q + 1] * w.w;
    }
    // reduce across the 16 feature lanes (both half-warps hold duplicates)
#pragma unroll
    for (int o = 8; o > 0; o >>= 1) {
        o0 += __shfl_xor_sync(0xffffffffu, o0, o);
        o1 += __shfl_xor_sync(0xffffffffu, o1, o);
    }
    if (lane == 0) {
        g_h2[2 * c + 0] = o0;
        g_h2[2 * c + 1] = o1;
    }
}

// ---------------- K6: layer-2 aggregation fused with mean-pool sums/counts ----------------
__global__ __launch_bounds__(256) void layer2_pool_kernel(const int* __restrict__ batch) {
    __shared__ float sp[NG * 2];
    __shared__ float sc[NG];
    int tid = threadIdx.x;
    if (tid < NG * 2) sp[tid] = 0.f;
    if (tid < NG) sc[tid] = 0.f;
    __syncthreads();

    int c = blockIdx.x * blockDim.x + tid;
    if (c < NN) {
        float dc = g_dinv[c];
        int start = g_off[c], end = g_off[c + 1];
        float e0 = 0.f, e1 = 0.f;
        const float2* h2v = (const float2*)g_h2;
        for (int idx = start; idx < end; idx++) {
            int r = g_csr[idx];
            float w = g_dinv[r];
            float2 v = h2v[r];
            e0 += w * v.x;
            e1 += w * v.y;
        }
        float2 self = h2v[c];
        float agg0 = dc * (e0 + dc * self.x);
        float agg1 = dc * (e1 + dc * self.y);
        int g = batch[c];
        g = min(max(g, 0), NG - 1);     // defensive clamp
        atomicAdd(&sp[2 * g + 0], agg0);
        atomicAdd(&sp[2 * g + 1], agg1);
        atomicAdd(&sc[g], 1.f);
    }
    __syncthreads();
    if (tid < NG) {
        if (sc[tid] != 0.f) atomicAdd(&g_cnt[tid], sc[tid]);
        if (sp[2 * tid] != 0.f || sp[2 * tid + 1] != 0.f) {
            atomicAdd(&g_pool[2 * tid + 0], sp[2 * tid + 0]);
            atomicAdd(&g_pool[2 * tid + 1], sp[2 * tid + 1]);
        }
    }
}

// ---------------- K7: mean + b2 + log_softmax ----------------
__global__ void finalize_kernel(float* __restrict__ out, const float* __restrict__ b2) {
    int g = threadIdx.x;
    if (g < NG) {
        float cc = fmaxf(g_cnt[g], 1.0f);
        float a = g_pool[2 * g + 0] / cc + b2[0];
        float b = g_pool[2 * g + 1] / cc + b2[1];
        float m = fmaxf(a, b);
        float lse = m + logf(expf(a - m) + expf(b - m));
        out[2 * g + 0] = a - lse;
        out[2 * g + 1] = b - lse;
    }
}

// ---------------- launch ----------------
extern "C" void kernel_launch(void* const* d_in, const int* in_sizes, int n_in,
                              void* d_out, int out_size) {
    // Bind inputs BY ELEMENT COUNT (all seven are pairwise distinct).
    const float* x     = (const float*)d_in[0];
    const int*   ei    = (const int*)(n_in > 1 ? d_in[1] : d_in[0]);
    const int*   batch = (const int*)(n_in > 2 ? d_in[2] : d_in[0]);
    const float* W1    = (const float*)(n_in > 3 ? d_in[3] : d_in[0]);
    const float* b1    = (const float*)(n_in > 4 ? d_in[4] : d_in[0]);
    const float* W2    = (const float*)(n_in > 5 ? d_in[5] : d_in[0]);
    const float* b2    = (const float*)(n_in > 6 ? d_in[6] : d_in[0]);
    for (int i = 0; i < n_in; i++) {
        long long sz = in_sizes[i];
        if (sz == (long long)NN * FIN)      x     = (const float*)d_in[i];
        else if (sz == 2LL * NE)            ei    = (const int*)d_in[i];
        else if (sz == NN)                  batch = (const int*)d_in[i];
        else if (sz == FIN * F1)            W1    = (const float*)d_in[i];
        else if (sz == F1)                  b1    = (const float*)d_in[i];
        else if (sz == F1 * 2)              W2    = (const float*)d_in[i];
        else if (sz == 2)                   b2    = (const float*)d_in[i];
    }
    float* out = (float*)d_out;

    // Fork a side stream for the edge pipeline: parallel branches in the captured
    // graph. Stream/events created fresh per call (deterministic, no device mem)
    // and deliberately leaked; replay never re-enters this function.
    cudaStream_t s2;
    cudaEvent_t evFork, evJoin;
    cudaStreamCreateWithFlags(&s2, cudaStreamNonBlocking);
    cudaEventCreateWithFlags(&evFork, cudaEventDisableTiming);
    cudaEventCreateWithFlags(&evJoin, cudaEventDisableTiming);

    // common prologue (both branches need g_degi zeroed / W1T converted)
    zero_w1t_kernel<<<(NN + 255) / 256, 256>>>(W1);
    cudaEventRecord(evFork, 0);
    cudaStreamWaitEvent(s2, evFork, 0);

    // branch B (side stream): edge pipeline — L2/atomic-bound
    hist_kernel<<<(NE + 255) / 256, 256, 0, s2>>>(ei);
    scanA_kernel<<<NB, 256, 0, s2>>>();
    scanC_kernel<<<(NN + 255) / 256, 256, 0, s2>>>();
    fill_csr_kernel<<<(NE + 255) / 256, 256, 0, s2>>>(ei);
    cudaEventRecord(evJoin, s2);

    // branch A (main stream): gemm — DRAM/tensor-bound, overlaps branch B
    gemm_kernel<<<GEMM_BLOCKS, 256>>>(x);

    // join, then the dependent tail
    cudaStreamWaitEvent(0, evJoin, 0);
    fused1_kernel<<<NN / 8, 256>>>(b1, W2);
    layer2_pool_kernel<<<(NN + 255) / 256, 256>>>(batch);
    finalize_kernel<<<1, 128>>>(out, b2);
}

// round 15
// speedup vs baseline: 1.2073x; 1.2073x over previous
#include <cuda_runtime.h>
#include <cuda_bf16.h>
#include <cstdint>

#define NN   100000      // nodes
#define NE   3200000     // edges (without self loops)
#define NPAD 100096      // nodes padded to 128 for GEMM tiles
#define NG   128         // graphs
#define FIN  768
#define F1   128
#define SCAN_CHUNK 1024
#define NB   ((NN + SCAN_CHUNK - 1) / SCAN_CHUNK)   // 98 scan blocks
#define GEMM_BLOCKS (NPAD / 128)                    // 782 (M128 tiles — R12 champion)

// ---------------- scratch (device globals; no allocations allowed) ----------------
__device__ alignas(16) int   g_csr[NE];
__device__ alignas(16) int   g_degi[NN];
__device__ alignas(16) int   g_cur[NN];
__device__ alignas(16) int   g_off[NN + 1];
__device__ alignas(16) int   g_bsum[NB];
__device__ alignas(16) float g_dinv[NN];
__device__ alignas(16) __nv_bfloat16 g_h1b[(size_t)NN * F1];   // bf16 h1 (25.6MB, L2-resident)
__device__ alignas(16) float g_h2[(size_t)NN * 2];
__device__ alignas(16) __nv_bfloat16 g_W1bT[(size_t)F1 * FIN]; // W1 transposed [128][768]
__device__ alignas(16) float g_pool[NG * 2];
__device__ alignas(16) float g_cnt[NG];

// ---------------- K0: zero scratch + W1 [768,128] fp32 -> W1T [128,768] bf16 -------
__global__ void zero_w1t_kernel(const float* __restrict__ W1) {
    int i = blockIdx.x * blockDim.x + threadIdx.x;
    if (i < NN) g_degi[i] = 0;
    if (i < NG * 2) g_pool[i] = 0.0f;
    if (i < NG) g_cnt[i] = 0.0f;
    if (i < FIN * F1) {
        int n = i / FIN;
        int k = i - n * FIN;
        g_W1bT[i] = __float2bfloat16(W1[(size_t)k * F1 + n]);
    }
}

// ---------------- K1: degree histogram over destination column (int32 edges) ------
__global__ void hist_kernel(const int* __restrict__ ei) {
    int e = blockIdx.x * blockDim.x + threadIdx.x;
    if (e < NE) {
        int c = ei[NE + e];
        c = min(max(c, 0), NN - 1);     // defensive: never scatter OOB
        atomicAdd(&g_degi[c], 1);
    }
}

// ---------------- K2a: per-block local exclusive scan (1024 elems/block) + dinv ----
__global__ __launch_bounds__(256) void scanA_kernel() {
    __shared__ int wsum[8];
    int tid = threadIdx.x, lane = tid & 31, wid = tid >> 5;
    int i0 = blockIdx.x * SCAN_CHUNK + tid * 4;
    int v0 = (i0 + 0 < NN) ? g_degi[i0 + 0] : 0;
    int v1 = (i0 + 1 < NN) ? g_degi[i0 + 1] : 0;
    int v2 = (i0 + 2 < NN) ? g_degi[i0 + 2] : 0;
    int v3 = (i0 + 3 < NN) ? g_degi[i0 + 3] : 0;
    int t = v0 + v1 + v2 + v3;
    int s = t;
#pragma unroll
    for (int o = 1; o < 32; o <<= 1) {
        int u = __shfl_up_sync(0xffffffffu, s, o);
        if (lane >= o) s += u;
    }
    if (lane == 31) wsum[wid] = s;
    __syncthreads();
    if (wid == 0 && lane < 8) {
        int ws = wsum[lane];
#pragma unroll
        for (int o = 1; o < 8; o <<= 1) {
            int u = __shfl_up_sync(0xffu, ws, o);
            if (lane >= o) ws += u;
        }
        wsum[lane] = ws;
    }
    __syncthreads();
    int warpbase = wid ? wsum[wid - 1] : 0;
    int excl = warpbase + (s - t);                 // local exclusive prefix
    int e0 = excl, e1 = e0 + v0, e2 = e1 + v1, e3 = e2 + v2;
    if (i0 + 0 < NN) { g_off[i0 + 0] = e0; g_dinv[i0 + 0] = rsqrtf((float)(v0 + 1)); }
    if (i0 + 1 < NN) { g_off[i0 + 1] = e1; g_dinv[i0 + 1] = rsqrtf((float)(v1 + 1)); }
    if (i0 + 2 < NN) { g_off[i0 + 2] = e2; g_dinv[i0 + 2] = rsqrtf((float)(v2 + 1)); }
    if (i0 + 3 < NN) { g_off[i0 + 3] = e3; g_dinv[i0 + 3] = rsqrtf((float)(v3 + 1)); }
    if (tid == 255) g_bsum[blockIdx.x] = wsum[7];  // block total
}

// ---------------- K2b: add block bases (each block warp-reduces its prefix) --------
__global__ __launch_bounds__(256) void scanC_kernel() {
    int blk = blockIdx.x;
    int chunk = blk >> 2;                 // 256-thread block sits inside one 1024-chunk
    int lane = threadIdx.x & 31;
    int acc = 0;
    for (int b = lane; b < chunk; b += 32) acc += g_bsum[b];
#pragma unroll
    for (int o = 16; o > 0; o >>= 1) acc += __shfl_xor_sync(0xffffffffu, acc, o);
    int i = blk * 256 + threadIdx.x;
    if (i < NN) {
        int o = g_off[i] + acc;
        g_off[i] = o;
        g_cur[i] = o;
    }
    if (i == 0) g_off[NN] = NE;
}

// ---------------- K3: fill CSR (bucketize source rows by destination col) ----------
__global__ void fill_csr_kernel(const int* __restrict__ ei) {
    int e = blockIdx.x * blockDim.x + threadIdx.x;
    if (e < NE) {
        int r = ei[e];
        int c = ei[NE + e];
        r = min(max(r, 0), NN - 1);
        c = min(max(c, 0), NN - 1);
        int pos = atomicAdd(&g_cur[c], 1);
        g_csr[pos] = r;
    }
}

// ---------------- K4: GEMM h1 = bf16(x) @ bf16(W1) -> bf16, mma.sync ---------------
// R12 champion form: M128xN128 tile, coalesced A staging, register double-buffering.
__device__ __forceinline__ void mma16816(float* d, const uint32_t* a, const uint32_t* b) {
    asm volatile(
        "mma.sync.aligned.m16n8k16.row.col.f32.bf16.bf16.f32 "
        "{%0,%1,%2,%3}, {%4,%5,%6,%7}, {%8,%9}, {%0,%1,%2,%3};\n"
        : "+f"(d[0]), "+f"(d[1]), "+f"(d[2]), "+f"(d[3])
        : "r"(a[0]), "r"(a[1]), "r"(a[2]), "r"(a[3]), "r"(b[0]), "r"(b[1]));
}

__global__ __launch_bounds__(256, 2) void gemm_kernel(const float* __restrict__ x) {
    __shared__ alignas(16) __nv_bfloat16 As[128][40];   // stride 40 elems: conflict-free frags
    __shared__ alignas(16) __nv_bfloat16 Bt[128][40];

    int tid = threadIdx.x;
    int warp = tid >> 5, lane = tid & 31;
    int wm = warp & 3;            // 4 warps over M (32 rows each)
    int wn = warp >> 2;           // 2 warps over N (64 cols each)
    int blockM = blockIdx.x * 128;
    int gid = lane >> 2;          // group id 0..7
    int qid = lane & 3;           // thread-in-group 0..3

    float acc[2][8][4];
#pragma unroll
    for (int mt = 0; mt < 2; mt++)
#pragma unroll
        for (int nt = 0; nt < 8; nt++)
#pragma unroll
            for (int i = 0; i < 4; i++) acc[mt][nt][i] = 0.0f;

    // staging maps: A — warp covers 4 consecutive rows (8 lanes x float4 = 128B/row)
    int srow = tid >> 3;          // 0..31 (pass p adds p*32)
    int sl8  = tid & 7;           // 0..7
    // B — 4 lanes x uint4 per n-row (64B row segment), 8 rows per warp
    int bn   = tid >> 2;          // 0..63 (pass s adds s*64)
    int bq   = tid & 3;           // 0..3

    const float* xbase = x + (size_t)blockM * FIN;

    float4 av[4];
    uint4  bv[2];

    // prefetch tile k0 = 0
#pragma unroll
    for (int p = 0; p < 4; p++) {
        int row = p * 32 + srow;
        bool ok = (blockM + row) < NN;
        av[p] = ok ? *(const float4*)(xbase + (size_t)row * FIN + sl8 * 4)
                   : make_float4(0.f, 0.f, 0.f, 0.f);
    }
#pragma unroll
    for (int s = 0; s < 2; s++) {
        int n = s * 64 + bn;
        bv[s] = *(const uint4*)(g_W1bT + (size_t)n * FIN + bq * 8);
    }

    for (int k0 = 0; k0 < FIN; k0 += 32) {
        // commit prefetched tile to smem
#pragma unroll
        for (int p = 0; p < 4; p++) {
            int row = p * 32 + srow;
            *(__nv_bfloat162*)&As[row][sl8 * 4 + 0] = __floats2bfloat162_rn(av[p].x, av[p].y);
            *(__nv_bfloat162*)&As[row][sl8 * 4 + 2] = __floats2bfloat162_rn(av[p].z, av[p].w);
        }
#pragma unroll
        for (int s = 0; s < 2; s++) {
            int n = s * 64 + bn;
            *(uint4*)&Bt[n][bq * 8] = bv[s];
        }
        __syncthreads();

        // issue next tile's global loads (latency hides behind the MMAs below)
        int kn = k0 + 32;
        if (kn < FIN) {
#pragma unroll
            for (int p = 0; p < 4; p++) {
                int row = p * 32 + srow;
                bool ok = (blockM + row) < NN;
                av[p] = ok ? *(const float4*)(xbase + (size_t)row * FIN + kn + sl8 * 4)
                           : make_float4(0.f, 0.f, 0.f, 0.f);
            }
#pragma unroll
            for (int s = 0; s < 2; s++) {
                int n = s * 64 + bn;
                bv[s] = *(const uint4*)(g_W1bT + (size_t)n * FIN + kn + bq * 8);
            }
        }

#pragma unroll
        for (int kk = 0; kk < 32; kk += 16) {
            uint32_t a[2][4], b[8][2];
#pragma unroll
            for (int mt = 0; mt < 2; mt++) {
                int row = wm * 32 + mt * 16 + gid;
                a[mt][0] = *(const uint32_t*)&As[row    ][kk + 2 * qid    ];
                a[mt][1] = *(const uint32_t*)&As[row + 8][kk + 2 * qid    ];
                a[mt][2] = *(const uint32_t*)&As[row    ][kk + 2 * qid + 8];
                a[mt][3] = *(const uint32_t*)&As[row + 8][kk + 2 * qid + 8];
            }
#pragma unroll
            for (int nt = 0; nt < 8; nt++) {
                int n = wn * 64 + nt * 8 + gid;
                b[nt][0] = *(const uint32_t*)&Bt[n][kk + 2 * qid    ];
                b[nt][1] = *(const uint32_t*)&Bt[n][kk + 2 * qid + 8];
            }
#pragma unroll
            for (int mt = 0; mt < 2; mt++)
#pragma unroll
                for (int nt = 0; nt < 8; nt++)
                    mma16816(acc[mt][nt], a[mt], b[nt]);
        }
        __syncthreads();
    }
    // store directly as bf16 h1
#pragma unroll
    for (int mt = 0; mt < 2; mt++) {
        int row = blockM + wm * 32 + mt * 16 + gid;
#pragma unroll
        for (int nt = 0; nt < 8; nt++) {
            int col = wn * 64 + nt * 8 + 2 * qid;
            if (row < NN)
                *(__nv_bfloat162*)(g_h1b + (size_t)row * F1 + col) =
                    __floats2bfloat162_rn(acc[mt][nt][0], acc[mt][nt][1]);
            if (row + 8 < NN)
                *(__nv_bfloat162*)(g_h1b + (size_t)(row + 8) * F1 + col) =
                    __floats2bfloat162_rn(acc[mt][nt][2], acc[mt][nt][3]);
        }
    }
}

// ---------------- K5: fused agg1 + b1 + relu + (@W2) -> h2[N,2] ----------------
// one warp per destination node; two edges in flight (one per half-warp);
// each lane owns 8 features (uint4 = 16B), accumulates in packed f32x2.
__device__ __forceinline__ void ffma2(unsigned long long& d, unsigned long long a,
                                      unsigned long long b) {
    asm("fma.rn.f32x2 %0, %1, %2, %0;" : "+l"(d) : "l"(a), "l"(b));
}
__device__ __forceinline__ unsigned long long bf2_to_f32x2(unsigned int v) {
    unsigned int lo = v << 16;
    unsigned int hi = v & 0xffff0000u;
    unsigned long long f2;
    asm("mov.b64 %0, {%1, %2};" : "=l"(f2) : "r"(lo), "r"(hi));
    return f2;
}

__global__ __launch_bounds__(256) void fused1_kernel(const float* __restrict__ b1,
                                                     const float* __restrict__ W2) {
    int warp = (blockIdx.x * blockDim.x + threadIdx.x) >> 5;
    int lane = threadIdx.x & 31;
    if (warp >= NN) return;
    int c = warp;
    float dc = g_dinv[c];
    int start = g_off[c], end = g_off[c + 1];
    int half = lane >> 4;                  // which edge of the pair
    int fl   = lane & 15;                  // feature lane: features fl*8 .. fl*8+7

    unsigned long long acc0 = 0, acc1 = 0, acc2 = 0, acc3 = 0;   // packed f32x2 (zeros)

    int idx = start + lane;
    int rl = (idx < end) ? g_csr[idx] : 0;
    float wl = (idx < end) ? g_dinv[rl] : 0.f;
    for (int base = start; base < end; base += 32) {
        // prefetch next chunk of edge indices/weights
        int nrl = 0; float nwl = 0.f;
        int nidx = base + 32 + lane;
        if (nidx < end) { nrl = g_csr[nidx]; nwl = g_dinv[nrl]; }
#pragma unroll
        for (int jj = 0; jj < 16; jj++) {
            int j = 2 * jj + half;
            int rr = __shfl_sync(0xffffffffu, rl, j);
            float ww = __shfl_sync(0xffffffffu, wl, j);
            unsigned long long wx;
            asm("mov.b64 %0, {%1, %1};" : "=l"(wx) : "f"(ww));
            uint4 p = *(const uint4*)(g_h1b + (size_t)rr * F1 + fl * 8);
            ffma2(acc0, bf2_to_f32x2(p.x), wx);
            ffma2(acc1, bf2_to_f32x2(p.y), wx);
            ffma2(acc2, bf2_to_f32x2(p.z), wx);
            ffma2(acc3, bf2_to_f32x2(p.w), wx);
        }
        rl = nrl; wl = nwl;
    }

    // unpack packed accumulators
    float s[8];
    asm("mov.b64 {%0, %1}, %2;" : "=f"(s[0]), "=f"(s[1]) : "l"(acc0));
    asm("mov.b64 {%0, %1}, %2;" : "=f"(s[2]), "=f"(s[3]) : "l"(acc1));
    asm("mov.b64 {%0, %1}, %2;" : "=f"(s[4]), "=f"(s[5]) : "l"(acc2));
    asm("mov.b64 {%0, %1}, %2;" : "=f"(s[6]), "=f"(s[7]) : "l"(acc3));
    // combine the two half-warp edge partitions (lanes l and l^16 hold same features)
#pragma unroll
    for (int i = 0; i < 8; i++) s[i] += __shfl_xor_sync(0xffffffffu, s[i], 16);

    // self loop: + dinv[c]^2 * h1[c]
    uint4 ps = *(const uint4*)(g_h1b + (size_t)c * F1 + fl * 8);
    float dc2 = dc * dc;
    s[0] += dc2 * __uint_as_float(ps.x << 16);
    s[1] += dc2 * __uint_as_float(ps.x & 0xffff0000u);
    s[2] += dc2 * __uint_as_float(ps.y << 16);
    s[3] += dc2 * __uint_as_float(ps.y & 0xffff0000u);
    s[4] += dc2 * __uint_as_float(ps.z << 16);
    s[5] += dc2 * __uint_as_float(ps.z & 0xffff0000u);
    s[6] += dc2 * __uint_as_float(ps.w << 16);
    s[7] += dc2 * __uint_as_float(ps.w & 0xffff0000u);

    // bias + relu
    int f0 = fl * 8;
    float4 ba = *(const float4*)(b1 + f0);
    float4 bb = *(const float4*)(b1 + f0 + 4);
    float t[8];
    t[0] = fmaxf(dc * s[0] + ba.x, 0.f);
    t[1] = fmaxf(dc * s[1] + ba.y, 0.f);
    t[2] = fmaxf(dc * s[2] + ba.z, 0.f);
    t[3] = fmaxf(dc * s[3] + ba.w, 0.f);
    t[4] = fmaxf(dc * s[4] + bb.x, 0.f);
    t[5] = fmaxf(dc * s[5] + bb.y, 0.f);
    t[6] = fmaxf(dc * s[6] + bb.z, 0.f);
    t[7] = fmaxf(dc * s[7] + bb.w, 0.f);

    // h2 = relu_vec @ W2  (W2 is [128,2] row-major; float4 covers 2 feature rows)
    float o0 = 0.f, o1 = 0.f;
#pragma unroll
    for (int q = 0; q < 4; q++) {
        float4 w = *(const float4*)(W2 + (size_t)(f0 + 2 * q) * 2);
        o0 += t[2 * q] * w.x + t[2 * q + 1] * w.z;
        o1 += t[2 * q] * w.y + t[2 * q + 1] * w.w;
    }
    // reduce across the 16 feature lanes (both half-warps hold duplicates)
#pragma unroll
    for (int o = 8; o > 0; o >>= 1) {
        o0 += __shfl_xor_sync(0xffffffffu, o0, o);
        o1 += __shfl_xor_sync(0xffffffffu, o1, o);
    }
    if (lane == 0) {
        g_h2[2 * c + 0] = o0;
        g_h2[2 * c + 1] = o1;
    }
}

// ---------------- K6: layer-2 aggregation fused with mean-pool sums/counts ----------------
__global__ __launch_bounds__(256) void layer2_pool_kernel(const int* __restrict__ batch) {
    __shared__ float sp[NG * 2];
    __shared__ float sc[NG];
    int tid = threadIdx.x;
    if (tid < NG * 2) sp[tid] = 0.f;
    if (tid < NG) sc[tid] = 0.f;
    __syncthreads();

    int c = blockIdx.x * blockDim.x + tid;
    if (c < NN) {
        float dc = g_dinv[c];
        int start = g_off[c], end = g_off[c + 1];
        float e0 = 0.f, e1 = 0.f;
        const float2* h2v = (const float2*)g_h2;
        for (int idx = start; idx < end; idx++) {
            int r = g_csr[idx];
            float w = g_dinv[r];
            float2 v = h2v[r];
            e0 += w * v.x;
            e1 += w * v.y;
        }
        float2 self = h2v[c];
        float agg0 = dc * (e0 + dc * self.x);
        float agg1 = dc * (e1 + dc * self.y);
        int g = batch[c];
        g = min(max(g, 0), NG - 1);     // defensive clamp
        atomicAdd(&sp[2 * g + 0], agg0);
        atomicAdd(&sp[2 * g + 1], agg1);
        atomicAdd(&sc[g], 1.f);
    }
    __syncthreads();
    if (tid < NG) {
        if (sc[tid] != 0.f) atomicAdd(&g_cnt[tid], sc[tid]);
        if (sp[2 * tid] != 0.f || sp[2 * tid + 1] != 0.f) {
            atomicAdd(&g_pool[2 * tid + 0], sp[2 * tid + 0]);
            atomicAdd(&g_pool[2 * tid + 1], sp[2 * tid + 1]);
        }
    }
}

// ---------------- K7: mean + b2 + log_softmax ----------------
__global__ void finalize_kernel(float* __restrict__ out, const float* __restrict__ b2) {
    int g = threadIdx.x;
    if (g < NG) {
        float cc = fmaxf(g_cnt[g], 1.0f);
        float a = g_pool[2 * g + 0] / cc + b2[0];
        float b = g_pool[2 * g + 1] / cc + b2[1];
        float m = fmaxf(a, b);
        float lse = m + logf(expf(a - m) + expf(b - m));
        out[2 * g + 0] = a - lse;
        out[2 * g + 1] = b - lse;
    }
}

// ---------------- launch ----------------
extern "C" void kernel_launch(void* const* d_in, const int* in_sizes, int n_in,
                              void* d_out, int out_size) {
    // Bind inputs BY ELEMENT COUNT (all seven are pairwise distinct).
    const float* x     = (const float*)d_in[0];
    const int*   ei    = (const int*)(n_in > 1 ? d_in[1] : d_in[0]);
    const int*   batch = (const int*)(n_in > 2 ? d_in[2] : d_in[0]);
    const float* W1    = (const float*)(n_in > 3 ? d_in[3] : d_in[0]);
    const float* b1    = (const float*)(n_in > 4 ? d_in[4] : d_in[0]);
    const float* W2    = (const float*)(n_in > 5 ? d_in[5] : d_in[0]);
    const float* b2    = (const float*)(n_in > 6 ? d_in[6] : d_in[0]);
    for (int i = 0; i < n_in; i++) {
        long long sz = in_sizes[i];
        if (sz == (long long)NN * FIN)      x     = (const float*)d_in[i];
        else if (sz == 2LL * NE)            ei    = (const int*)d_in[i];
        else if (sz == NN)                  batch = (const int*)d_in[i];
        else if (sz == FIN * F1)            W1    = (const float*)d_in[i];
        else if (sz == F1)                  b1    = (const float*)d_in[i];
        else if (sz == F1 * 2)              W2    = (const float*)d_in[i];
        else if (sz == 2)                   b2    = (const float*)d_in[i];
    }
    float* out = (float*)d_out;

    // Fork a side stream for the edge pipeline: parallel branches in the captured
    // graph. Stream/events created fresh per call (deterministic, no device mem)
    // and deliberately leaked; replay never re-enters this function.
    cudaStream_t s2;
    cudaEvent_t evFork, evJoin;
    cudaStreamCreateWithFlags(&s2, cudaStreamNonBlocking);
    cudaEventCreateWithFlags(&evFork, cudaEventDisableTiming);
    cudaEventCreateWithFlags(&evJoin, cudaEventDisableTiming);

    // common prologue (both branches need g_degi zeroed / W1T converted)
    zero_w1t_kernel<<<(NN + 255) / 256, 256>>>(W1);
    cudaEventRecord(evFork, 0);
    cudaStreamWaitEvent(s2, evFork, 0);

    // branch A (main stream): gemm — enqueued FIRST so replay dispatches its
    // CTAs ahead of the edge pipeline's 12.5K blocks; branch B backfills.
    gemm_kernel<<<GEMM_BLOCKS, 256>>>(x);

    // branch B (side stream): edge pipeline — L2/atomic-bound
    hist_kernel<<<(NE + 255) / 256, 256, 0, s2>>>(ei);
    scanA_kernel<<<NB, 256, 0, s2>>>();
    scanC_kernel<<<(NN + 255) / 256, 256, 0, s2>>>();
    fill_csr_kernel<<<(NE + 255) / 256, 256, 0, s2>>>(ei);
    cudaEventRecord(evJoin, s2);

    // join, then the dependent tail
    cudaStreamWaitEvent(0, evJoin, 0);
    fused1_kernel<<<NN / 8, 256>>>(b1, W2);
    layer2_pool_kernel<<<(NN + 255) / 256, 256>>>(batch);
    finalize_kernel<<<1, 128>>>(out, b2);
}